// round 15
// baseline (speedup 1.0000x reference)
#include <cuda_runtime.h>
#include <cuda_fp16.h>

// Shifted-window attention, fused per-window, fp16 mma.sync + ldmatrix.
// B=2, C=128, U=V=5, H=W=64, WS=8, SHIFT=4, heads=4, d=32. 3200 windows.
// One CTA per window, 256 threads (8 warps), 2 CTAs/SM.
// P (attention probs) kept entirely in registers (S-frag == PV A-frag).
// Weights pre-converted to fp16 once by a prologue kernel into g_wfp16
// (rows 0..383 = qkv_w, rows 384..511 = proj_w; stride 136 halves).

#define NWIN 3200
#define SCALE_F 0.17677669529663689f

// smem layout (byte offsets). Word-strides chosen != 0 mod 8 words for
// conflict-free ldmatrix phases.
#define XST_OFF    0        // gather: channel-major [128][72] halves
#define XST_STRIDE 72
#define OA_STRIDE  136      // attention out, token-major [64][136] halves (overlays XST)
#define QKV_OFF    18432    // [64][392] halves
#define QKV_STRIDE 392
#define WST_OFF    68608    // [128][136] halves, weights [out][in]
#define WST_STRIDE 136
#define RPB_OFF    103424   // 900 fp32
#define POUT_OFF   18432    // fp32 [64][132], overlays QKV
#define POUT_STRIDE 132
#define SMEM_BYTES 107024

__device__ __half g_wfp16[512 * 136];   // pre-converted weights, pre-strided

__device__ __forceinline__ unsigned int smem_u32(const void* p) {
    unsigned int a;
    asm("{ .reg .u64 t; cvta.to.shared.u64 t, %1; cvt.u32.u64 %0, t; }"
        : "=r"(a) : "l"(p));
    return a;
}
__device__ __forceinline__ void ldsm_x4(unsigned int r[4], unsigned int addr) {
    asm volatile("ldmatrix.sync.aligned.m8n8.x4.shared.b16 {%0,%1,%2,%3}, [%4];"
                 : "=r"(r[0]), "=r"(r[1]), "=r"(r[2]), "=r"(r[3]) : "r"(addr));
}
__device__ __forceinline__ void ldsm_x4t(unsigned int r[4], unsigned int addr) {
    asm volatile("ldmatrix.sync.aligned.m8n8.x4.trans.shared.b16 {%0,%1,%2,%3}, [%4];"
                 : "=r"(r[0]), "=r"(r[1]), "=r"(r[2]), "=r"(r[3]) : "r"(addr));
}
__device__ __forceinline__ void mma_f16(float d[4], const unsigned int a[4],
                                        unsigned int b0, unsigned int b1) {
    asm volatile("mma.sync.aligned.m16n8k16.row.col.f32.f16.f16.f32 "
                 "{%0,%1,%2,%3},{%4,%5,%6,%7},{%8,%9},{%0,%1,%2,%3};"
                 : "+f"(d[0]), "+f"(d[1]), "+f"(d[2]), "+f"(d[3])
                 : "r"(a[0]), "r"(a[1]), "r"(a[2]), "r"(a[3]), "r"(b0), "r"(b1));
}
__device__ __forceinline__ unsigned int pack2(float a, float b) {
    __half2 h = __floats2half2_rn(a, b);
    return *(unsigned int*)&h;
}

// ---- prologue: fp32 weights -> fp16, pre-strided (one-time, 16384 threads) ----
__global__ void convert_weights_kernel(const float* __restrict__ qkv_w,
                                       const float* __restrict__ proj_w) {
    int idx = blockIdx.x * 256 + threadIdx.x;     // 0..16383, 4 elems each
    int row = idx >> 5, c4 = (idx & 31) * 4;      // 512 rows x 128 cols
    const float* src = (row < 384) ? &qkv_w[row * 128 + c4]
                                   : &proj_w[(row - 384) * 128 + c4];
    float4 t = *(const float4*)src;
    __half2 h0 = __floats2half2_rn(t.x, t.y);
    __half2 h1 = __floats2half2_rn(t.z, t.w);
    *(uint2*)&g_wfp16[row * 136 + c4] =
        make_uint2(*(unsigned int*)&h0, *(unsigned int*)&h1);
}

// Pure fp16 copy staging: 8x LDG.128 + 8x STS.128 per thread, no cvt.
__device__ __forceinline__ void stage_weights(char* smc, int baseRow, int tid) {
    __half* wst = (__half*)(smc + WST_OFF);
    const __half* src = g_wfp16 + baseRow * 136;
    #pragma unroll
    for (int j = 0; j < 8; j++) {
        int chunk = tid + 256 * j;                 // 0..2047
        int r = chunk >> 4, cc = (chunk & 15) * 8; // 128 rows x 16 chunks(16B)
        *(uint4*)(wst + r * WST_STRIDE + cc) = *(const uint4*)(src + r * 136 + cc);
    }
}

__global__ void __launch_bounds__(256, 2) win_attn_kernel(
    const float* __restrict__ x,
    const float* __restrict__ qkv_b,
    const float* __restrict__ proj_b,
    const float* __restrict__ rpb_table,
    float* __restrict__ out)
{
    extern __shared__ char smc[];
    const unsigned int smb = smem_u32(smc);
    float* rpb = (float*)(smc + RPB_OFF);

    const int tid  = threadIdx.x;
    const int warp = tid >> 5, lane = tid & 31;
    const int g  = lane >> 2;
    const int tg = lane & 3;
    const int lq = lane & 15;
    const int hi8 = (lane >> 4) << 3;     // 0 or 8 (k half)

    const int w  = blockIdx.x;
    const int wn = w & 7;
    const int hn = (w >> 3) & 7;
    const int v  = (w / 64) % 5;
    const int u  = (w / 320) % 5;
    const int b  = w / 1600;

    for (int i = tid; i < 900; i += 256) rpb[i] = rpb_table[i];

    const int bbase = b * (128 * 102400) + (u * 5 + v) * 4096;
    const int h0 = hn * 8, w0 = wn * 8;

    // ---- Phase 1: gather (vectorized) -> Xst[channel][token] fp16 ----
    {
        __half* xst = (__half*)(smc + XST_OFF);
        #pragma unroll
        for (int it = 0; it < 8; it++) {
            int idx = tid + it * 256;       // 2048 = 128 c x 16 (row,half)
            int rh = idx & 15, c = idx >> 4;
            int wv = rh >> 1, hf = rh & 1;
            int hg = (h0 + wv + 60) & 63;
            int wg = (w0 + hf * 4 + 60) & 63;   // 16B aligned, no wrap inside 4
            float4 t = *(const float4*)&x[bbase + c * 102400 + hg * 64 + wg];
            __half2 h0p = __floats2half2_rn(t.x, t.y);
            __half2 h1p = __floats2half2_rn(t.z, t.w);
            uint2 pkt = make_uint2(*(unsigned int*)&h0p, *(unsigned int*)&h1p);
            *(uint2*)(xst + c * XST_STRIDE + wv * 8 + hf * 4) = pkt;
        }
    }
    __syncthreads();

    const int m0 = (warp >> 2) * 32;   // 0 or 32
    const int n0 = (warp & 3) * 32;    // 0,32,64,96

    // trans-A lane addressing (A stored k-major [c][token])
    const int tKrow = (lane & 7) + hi8;
    const int tMcol = lane & 8;

    // ---- Phase 2: qkv GEMM [64x128]x[128x384]^T, 3 passes ----
    for (int p = 0; p < 3; p++) {
        stage_weights(smc, p * 128, tid);
        __syncthreads();

        float acc[2][4][4];
        #pragma unroll
        for (int mt = 0; mt < 2; mt++)
            #pragma unroll
            for (int nt = 0; nt < 4; nt++)
                #pragma unroll
                for (int e = 0; e < 4; e++) acc[mt][nt][e] = 0.f;

        #pragma unroll 4
        for (int k0 = 0; k0 < 128; k0 += 16) {
            unsigned int a[2][4];
            #pragma unroll
            for (int mt = 0; mt < 2; mt++)
                ldsm_x4t(a[mt], smb + XST_OFF +
                         (((k0 + tKrow) * XST_STRIDE) + m0 + mt * 16 + tMcol) * 2);
            #pragma unroll
            for (int ntp = 0; ntp < 2; ntp++) {
                unsigned int bf[4];
                ldsm_x4(bf, smb + WST_OFF +
                        (((n0 + ntp * 16 + lq) * WST_STRIDE) + k0 + hi8) * 2);
                mma_f16(acc[0][2 * ntp],     a[0], bf[0], bf[2]);
                mma_f16(acc[0][2 * ntp + 1], a[0], bf[1], bf[3]);
                mma_f16(acc[1][2 * ntp],     a[1], bf[0], bf[2]);
                mma_f16(acc[1][2 * ntp + 1], a[1], bf[1], bf[3]);
            }
        }

        __half2* qkv2 = (__half2*)(smc + QKV_OFF);
        #pragma unroll
        for (int mt = 0; mt < 2; mt++)
            #pragma unroll
            for (int nt = 0; nt < 4; nt++) {
                int col0 = n0 + nt * 8 + 2 * tg;
                float b0 = qkv_b[p * 128 + col0];
                float b1 = qkv_b[p * 128 + col0 + 1];
                int r0 = m0 + mt * 16 + g, r1 = r0 + 8;
                int cofs = (p * 128 + col0) >> 1;
                qkv2[(r0 * QKV_STRIDE) / 2 + cofs] =
                    __floats2half2_rn(acc[mt][nt][0] + b0, acc[mt][nt][1] + b1);
                qkv2[(r1 * QKV_STRIDE) / 2 + cofs] =
                    __floats2half2_rn(acc[mt][nt][2] + b0, acc[mt][nt][3] + b1);
            }
        __syncthreads();
    }

    // stage proj weights now (Wst free; overlaps with attention below)
    stage_weights(smc, 384, tid);

    // ---- Phase 3: attention, 2 warps/head; P stays in registers ----
    {
        const int h = warp >> 1, hw = warp & 1;
        const int rbase = hw * 32;
        const int qcol = h * 96, kcol = qcol + 32, vcol = qcol + 64;

        float S[2][8][4];
        #pragma unroll
        for (int mt = 0; mt < 2; mt++)
            #pragma unroll
            for (int nt = 0; nt < 8; nt++)
                #pragma unroll
                for (int e = 0; e < 4; e++) S[mt][nt][e] = 0.f;

        #pragma unroll
        for (int k0 = 0; k0 < 32; k0 += 16) {
            unsigned int a[2][4];
            #pragma unroll
            for (int mt = 0; mt < 2; mt++)
                ldsm_x4(a[mt], smb + QKV_OFF +
                        (((rbase + mt * 16 + lq) * QKV_STRIDE) + qcol + k0 + hi8) * 2);
            #pragma unroll
            for (int ntp = 0; ntp < 4; ntp++) {
                unsigned int bf[4];
                ldsm_x4(bf, smb + QKV_OFF +
                        (((ntp * 16 + lq) * QKV_STRIDE) + kcol + k0 + hi8) * 2);
                mma_f16(S[0][2 * ntp],     a[0], bf[0], bf[2]);
                mma_f16(S[0][2 * ntp + 1], a[0], bf[1], bf[3]);
                mma_f16(S[1][2 * ntp],     a[1], bf[0], bf[2]);
                mma_f16(S[1][2 * ntp + 1], a[1], bf[1], bf[3]);
            }
        }

        // scale + rel-pos bias, row max (rows g, g+8 per mt)
        float mx[4] = {-1e30f, -1e30f, -1e30f, -1e30f};
        #pragma unroll
        for (int mt = 0; mt < 2; mt++)
            #pragma unroll
            for (int nt = 0; nt < 8; nt++)
                #pragma unroll
                for (int e = 0; e < 4; e++) {
                    int row = rbase + mt * 16 + g + ((e >> 1) << 3);
                    int col = nt * 8 + 2 * tg + (e & 1);
                    int qi = row >> 3, qj = row & 7, ki = col >> 3, kj = col & 7;
                    int bidx = (qi - ki + 7) * 15 + (qj - kj + 7);
                    float sv = S[mt][nt][e] * SCALE_F + rpb[bidx * 4 + h];
                    S[mt][nt][e] = sv;
                    int slot = mt * 2 + (e >> 1);
                    mx[slot] = fmaxf(mx[slot], sv);
                }
        #pragma unroll
        for (int s4 = 0; s4 < 4; s4++) {
            mx[s4] = fmaxf(mx[s4], __shfl_xor_sync(0xffffffffu, mx[s4], 1));
            mx[s4] = fmaxf(mx[s4], __shfl_xor_sync(0xffffffffu, mx[s4], 2));
        }
        float sum[4] = {0.f, 0.f, 0.f, 0.f};
        #pragma unroll
        for (int mt = 0; mt < 2; mt++)
            #pragma unroll
            for (int nt = 0; nt < 8; nt++)
                #pragma unroll
                for (int e = 0; e < 4; e++) {
                    int slot = mt * 2 + (e >> 1);
                    float ev = __expf(S[mt][nt][e] - mx[slot]);
                    S[mt][nt][e] = ev;
                    sum[slot] += ev;
                }
        #pragma unroll
        for (int s4 = 0; s4 < 4; s4++) {
            sum[s4] += __shfl_xor_sync(0xffffffffu, sum[s4], 1);
            sum[s4] += __shfl_xor_sync(0xffffffffu, sum[s4], 2);
        }
        float inv[4];
        #pragma unroll
        for (int s4 = 0; s4 < 4; s4++) inv[s4] = 1.f / sum[s4];

        // pack P (unnormalized) directly into PV A-fragments: S-tile pair
        // (nt=2kp, 2kp+1) == A m16k16 fragment for kstep kp.
        unsigned int aP[2][4][4];
        #pragma unroll
        for (int mt = 0; mt < 2; mt++)
            #pragma unroll
            for (int kp = 0; kp < 4; kp++) {
                aP[mt][kp][0] = pack2(S[mt][2 * kp][0],     S[mt][2 * kp][1]);
                aP[mt][kp][1] = pack2(S[mt][2 * kp][2],     S[mt][2 * kp][3]);
                aP[mt][kp][2] = pack2(S[mt][2 * kp + 1][0], S[mt][2 * kp + 1][1]);
                aP[mt][kp][3] = pack2(S[mt][2 * kp + 1][2], S[mt][2 * kp + 1][3]);
            }

        // O = P.V : M=32, N=32, K=64. V via ldmatrix.x4.trans from [token][d].
        float O[2][4][4];
        #pragma unroll
        for (int mt = 0; mt < 2; mt++)
            #pragma unroll
            for (int nt = 0; nt < 4; nt++)
                #pragma unroll
                for (int e = 0; e < 4; e++) O[mt][nt][e] = 0.f;

        #pragma unroll
        for (int kp = 0; kp < 4; kp++) {
            #pragma unroll
            for (int vp = 0; vp < 2; vp++) {
                unsigned int bf[4];
                ldsm_x4t(bf, smb + QKV_OFF +
                         (((kp * 16 + lq) * QKV_STRIDE) + vcol + vp * 16 + hi8) * 2);
                mma_f16(O[0][2 * vp],     aP[0][kp], bf[0], bf[1]);
                mma_f16(O[0][2 * vp + 1], aP[0][kp], bf[2], bf[3]);
                mma_f16(O[1][2 * vp],     aP[1][kp], bf[0], bf[1]);
                mma_f16(O[1][2 * vp + 1], aP[1][kp], bf[2], bf[3]);
            }
        }

        // normalize, write merged-head Oa fp16 token-major (overlays Xst)
        __half2* oa2 = (__half2*)(smc + XST_OFF);
        #pragma unroll
        for (int mt = 0; mt < 2; mt++)
            #pragma unroll
            for (int nt = 0; nt < 4; nt++) {
                int col0 = h * 32 + nt * 8 + 2 * tg;
                int r0 = rbase + mt * 16 + g, r1 = r0 + 8;
                int s0 = mt * 2, s1 = mt * 2 + 1;
                oa2[(r0 * OA_STRIDE + col0) / 2] = __floats2half2_rn(
                    O[mt][nt][0] * inv[s0], O[mt][nt][1] * inv[s0]);
                oa2[(r1 * OA_STRIDE + col0) / 2] = __floats2half2_rn(
                    O[mt][nt][2] * inv[s1], O[mt][nt][3] * inv[s1]);
            }
    }
    __syncthreads();   // Oa + proj weights visible

    // ---- Phase 4: proj GEMM [64x128]x[128x128]^T ----
    {
        float acc[2][4][4];
        #pragma unroll
        for (int mt = 0; mt < 2; mt++)
            #pragma unroll
            for (int nt = 0; nt < 4; nt++)
                #pragma unroll
                for (int e = 0; e < 4; e++) acc[mt][nt][e] = 0.f;

        #pragma unroll 4
        for (int k0 = 0; k0 < 128; k0 += 16) {
            unsigned int a[2][4];
            #pragma unroll
            for (int mt = 0; mt < 2; mt++)
                ldsm_x4(a[mt], smb + XST_OFF +
                        (((m0 + mt * 16 + lq) * OA_STRIDE) + k0 + hi8) * 2);
            #pragma unroll
            for (int ntp = 0; ntp < 2; ntp++) {
                unsigned int bf[4];
                ldsm_x4(bf, smb + WST_OFF +
                        (((n0 + ntp * 16 + lq) * WST_STRIDE) + k0 + hi8) * 2);
                mma_f16(acc[0][2 * ntp],     a[0], bf[0], bf[2]);
                mma_f16(acc[0][2 * ntp + 1], a[0], bf[1], bf[3]);
                mma_f16(acc[1][2 * ntp],     a[1], bf[0], bf[2]);
                mma_f16(acc[1][2 * ntp + 1], a[1], bf[1], bf[3]);
            }
        }

        float* Pout = (float*)(smc + POUT_OFF);
        #pragma unroll
        for (int mt = 0; mt < 2; mt++)
            #pragma unroll
            for (int nt = 0; nt < 4; nt++) {
                int col0 = n0 + nt * 8 + 2 * tg;
                float b0 = proj_b[col0], b1 = proj_b[col0 + 1];
                int r0 = m0 + mt * 16 + g, r1 = r0 + 8;
                *(float2*)&Pout[r0 * POUT_STRIDE + col0] =
                    make_float2(acc[mt][nt][0] + b0, acc[mt][nt][1] + b1);
                *(float2*)&Pout[r1 * POUT_STRIDE + col0] =
                    make_float2(acc[mt][nt][2] + b0, acc[mt][nt][3] + b1);
            }
    }
    __syncthreads();

    // ---- Phase 5: scatter (vectorized) with reverse shift ----
    {
        const float* Pout = (const float*)(smc + POUT_OFF);
        #pragma unroll
        for (int it = 0; it < 8; it++) {
            int idx = tid + it * 256;
            int c = idx & 127, rh = (idx >> 7) & 15;
            int wv = rh >> 1, hf = rh & 1;
            int s0 = wv * 8 + hf * 4;
            float4 t;
            t.x = Pout[(s0 + 0) * POUT_STRIDE + c];
            t.y = Pout[(s0 + 1) * POUT_STRIDE + c];
            t.z = Pout[(s0 + 2) * POUT_STRIDE + c];
            t.w = Pout[(s0 + 3) * POUT_STRIDE + c];
            int hg = (h0 + wv + 60) & 63;
            int wg = (w0 + hf * 4 + 60) & 63;
            *(float4*)&out[bbase + c * 102400 + hg * 64 + wg] = t;
        }
    }
}

extern "C" void kernel_launch(void* const* d_in, const int* in_sizes, int n_in,
                              void* d_out, int out_size)
{
    const float* x      = (const float*)d_in[0];
    const float* qkv_w  = (const float*)d_in[1];
    const float* qkv_b  = (const float*)d_in[2];
    const float* proj_w = (const float*)d_in[3];
    const float* proj_b = (const float*)d_in[4];
    const float* rpb    = (const float*)d_in[5];
    float* out = (float*)d_out;

    convert_weights_kernel<<<64, 256>>>(qkv_w, proj_w);

    cudaFuncSetAttribute(win_attn_kernel,
                         cudaFuncAttributeMaxDynamicSharedMemorySize, SMEM_BYTES);
    win_attn_kernel<<<NWIN, 256, SMEM_BYTES>>>(x, qkv_b, proj_b, rpb, out);
}